// round 3
// baseline (speedup 1.0000x reference)
#include <cuda_runtime.h>
#include <stdint.h>

#define NPTS 256
#define DIM  256
#define KNN  16
#define NB   128        // 2 rows/block; 128 < 148 SMs -> single-wave, spin barrier safe
#define EPSV 1e-12f

__device__ float g_Yn[NPTS * DIM];    // row-major normalized yi
__device__ float g_rn[NPTS];          // ||yn_j||^2
__device__ float g_part[NPTS];
__device__ unsigned g_bar = 0, g_rel = 0, g_done = 0;

__device__ __forceinline__ unsigned long long umin64(unsigned long long a,
                                                     unsigned long long b) {
    return a < b ? a : b;
}

__global__ __launch_bounds__(256, 1)
void k_fused(const float* __restrict__ yi, const float* __restrict__ yit,
             float* __restrict__ out) {
    __shared__ float4 s4[DIM];          // (yn_r0, ytn_r0, yn_r1, ytn_r1) per channel
    __shared__ float4 sh4[8];
    __shared__ float2 sh2[8];
    __shared__ float  sh_d1[2][NPTS];
    __shared__ float  sh_d2[2][NPTS];
    __shared__ float  sh_sc[6];         // rn0 rn1 rt0 rt1 dself0 dself1
    __shared__ float  shred[8];
    __shared__ unsigned s_last;

    const int t = threadIdx.x, b = blockIdx.x;
    const int r0 = 2 * b, r1 = r0 + 1;
    const int w = t >> 5, l = t & 31;

    unsigned epoch = 0;
    if (t == 0) epoch = *((volatile unsigned*)&g_rel);

    // ---------- Phase A: normalize rows r0,r1 (4 sums in one pass, 2 barriers) ----------
    float a0 = yi [r0 * DIM + t], c0 = yit[r0 * DIM + t];
    float a1 = yi [r1 * DIM + t], c1 = yit[r1 * DIM + t];

    float4 p = make_float4(a0 * a0, c0 * c0, a1 * a1, c1 * c1);
    #pragma unroll
    for (int o = 16; o; o >>= 1) {
        p.x += __shfl_down_sync(0xffffffffu, p.x, o);
        p.y += __shfl_down_sync(0xffffffffu, p.y, o);
        p.z += __shfl_down_sync(0xffffffffu, p.z, o);
        p.w += __shfl_down_sync(0xffffffffu, p.w, o);
    }
    if (l == 0) sh4[w] = p;
    __syncthreads();
    if (w == 0) {
        float4 q = (l < 8) ? sh4[l] : make_float4(0.f, 0.f, 0.f, 0.f);
        #pragma unroll
        for (int o = 4; o; o >>= 1) {
            q.x += __shfl_down_sync(0xffffffffu, q.x, o);
            q.y += __shfl_down_sync(0xffffffffu, q.y, o);
            q.z += __shfl_down_sync(0xffffffffu, q.z, o);
            q.w += __shfl_down_sync(0xffffffffu, q.w, o);
        }
        if (l == 0) sh4[0] = q;
    }
    __syncthreads();
    float4 S = sh4[0];                       // sa0, sc0, sa1, sc1

    float ia0 = 1.0f / sqrtf(S.x + EPSV), ic0 = 1.0f / sqrtf(S.y + EPSV);
    float ia1 = 1.0f / sqrtf(S.z + EPSV), ic1 = 1.0f / sqrtf(S.w + EPSV);
    float an0 = a0 * ia0, cn0 = c0 * ic0;
    float an1 = a1 * ia1, cn1 = c1 * ic1;

    g_Yn[r0 * DIM + t] = an0;                // coalesced row-major stores
    g_Yn[r1 * DIM + t] = an1;
    s4[t] = make_float4(an0, cn0, an1, cn1);

    float d0 = an0 - cn0, d1x = an1 - cn1;
    float2 p2 = make_float2(d0 * d0, d1x * d1x);
    #pragma unroll
    for (int o = 16; o; o >>= 1) {
        p2.x += __shfl_down_sync(0xffffffffu, p2.x, o);
        p2.y += __shfl_down_sync(0xffffffffu, p2.y, o);
    }
    if (l == 0) sh2[w] = p2;
    __syncthreads();
    if (t == 0) {
        float sd0 = 0.f, sd1 = 0.f;
        #pragma unroll
        for (int m = 0; m < 8; m++) { sd0 += sh2[m].x; sd1 += sh2[m].y; }
        float rn0 = S.x * ia0 * ia0, rn1 = S.z * ia1 * ia1;
        sh_sc[0] = rn0;              sh_sc[1] = rn1;
        sh_sc[2] = S.y * ic0 * ic0;  sh_sc[3] = S.w * ic1 * ic1;
        sh_sc[4] = 0.5f * sqrtf(sd0 + EPSV);
        sh_sc[5] = 0.5f * sqrtf(sd1 + EPSV);
        g_rn[r0] = rn0;              g_rn[r1] = rn1;
    }

    // ---------- software grid barrier ----------
    __threadfence();
    __syncthreads();
    if (t == 0) {
        unsigned arrived = atomicAdd(&g_bar, 1);
        if (arrived == NB - 1) {
            *((volatile unsigned*)&g_bar) = 0;
            __threadfence();
            atomicAdd(&g_rel, 1);
        } else {
            while (*((volatile unsigned*)&g_rel) == epoch) __nanosleep(32);
        }
        __threadfence();
    }
    __syncthreads();

    // ---------- Phase B: thread t = column j; vectorized row-t stream ----------
    const float4* __restrict__ vrow = (const float4*)(g_Yn) + t * (DIM / 4);
    float accn0 = 0.f, acct0 = 0.f, accn1 = 0.f, acct1 = 0.f;
    #pragma unroll 8
    for (int c4 = 0; c4 < DIM / 4; c4++) {
        float4 v  = vrow[c4];                // LDG.128, line reused across 8 iters (L1)
        float4 s0 = s4[4 * c4 + 0];
        float4 s1 = s4[4 * c4 + 1];
        float4 s2 = s4[4 * c4 + 2];
        float4 s3 = s4[4 * c4 + 3];
        accn0 = fmaf(s0.x, v.x, accn0); accn0 = fmaf(s1.x, v.y, accn0);
        accn0 = fmaf(s2.x, v.z, accn0); accn0 = fmaf(s3.x, v.w, accn0);
        acct0 = fmaf(s0.y, v.x, acct0); acct0 = fmaf(s1.y, v.y, acct0);
        acct0 = fmaf(s2.y, v.z, acct0); acct0 = fmaf(s3.y, v.w, acct0);
        accn1 = fmaf(s0.z, v.x, accn1); accn1 = fmaf(s1.z, v.y, accn1);
        accn1 = fmaf(s2.z, v.z, accn1); accn1 = fmaf(s3.z, v.w, accn1);
        acct1 = fmaf(s0.w, v.x, acct1); acct1 = fmaf(s1.w, v.y, acct1);
        acct1 = fmaf(s2.w, v.z, acct1); acct1 = fmaf(s3.w, v.w, acct1);
    }
    float rnj = *((volatile float*)&g_rn[t]);
    float rn0 = sh_sc[0], rn1 = sh_sc[1], rt0 = sh_sc[2], rt1 = sh_sc[3];
    sh_d1[0][t] = 0.5f * sqrtf(fmaxf(rn0 + rnj - 2.f * accn0, 0.f) + EPSV);
    sh_d2[0][t] = 0.5f * sqrtf(fmaxf(rt0 + rnj - 2.f * acct0, 0.f) + EPSV);
    sh_d1[1][t] = 0.5f * sqrtf(fmaxf(rn1 + rnj - 2.f * accn1, 0.f) + EPSV);
    sh_d2[1][t] = 0.5f * sqrtf(fmaxf(rt1 + rnj - 2.f * acct1, 0.f) + EPSV);
    __syncthreads();

    // ---------- Selection: warp w handles row r0+w (iterative exact argmin) ----------
    if (w < 2) {
        const int    row = r0 + w;
        const float* D1  = sh_d1[w];
        const float* D2  = sh_d2[w];
        unsigned long long k[8];
        #pragma unroll
        for (int m = 0; m < 8; m++) {
            int j = m * 32 + l;
            k[m] = ((unsigned long long)__float_as_uint(D1[j]) << 32) | (unsigned)j;
            if (j == row) k[m] = ~0ull;
        }
        float acc = 0.f, first = 0.f;
        for (int it = 0; it < KNN; it++) {
            unsigned long long m01 = umin64(k[0], k[1]);
            unsigned long long m23 = umin64(k[2], k[3]);
            unsigned long long m45 = umin64(k[4], k[5]);
            unsigned long long m67 = umin64(k[6], k[7]);
            unsigned long long best = umin64(umin64(m01, m23), umin64(m45, m67));
            #pragma unroll
            for (int o = 16; o; o >>= 1) {   // butterfly: every lane gets the min
                unsigned long long u = __shfl_xor_sync(0xffffffffu, best, o);
                best = umin64(best, u);
            }
            int   jw  = (int)(best & 0xffffffffull);
            float d1w = __uint_as_float((unsigned)(best >> 32));
            if (it == 0) first = d1w;
            float diff = d1w - D2[jw];
            acc = fmaf(diff, diff, acc);
            if (l == (jw & 31)) k[jw >> 5] = ~0ull;
        }
        if (l == 0) {
            g_part[row] = (acc - (float)KNN * 0.0025f)
                        + fmaxf(sh_sc[4 + w] + 0.6f - first, 0.f);
        }
    }

    // ---------- last arriving block: deterministic final reduce ----------
    __threadfence();
    __syncthreads();
    if (t == 0) s_last = atomicAdd(&g_done, 1);
    __syncthreads();
    if (s_last == NB - 1) {
        float v = *((volatile float*)&g_part[t]);
        #pragma unroll
        for (int o = 16; o; o >>= 1) v += __shfl_down_sync(0xffffffffu, v, o);
        if (l == 0) shred[w] = v;
        __syncthreads();
        if (w == 0) {
            float r = (l < 8) ? shred[l] : 0.f;
            #pragma unroll
            for (int o = 4; o; o >>= 1) r += __shfl_down_sync(0xffffffffu, r, o);
            if (l == 0) {
                out[0] = r;
                *((volatile unsigned*)&g_done) = 0;   // reset for next replay
            }
        }
    }
}

extern "C" void kernel_launch(void* const* d_in, const int* in_sizes, int n_in,
                              void* d_out, int out_size) {
    const float* yi  = (const float*)d_in[0];
    const float* yit = (const float*)d_in[1];
    k_fused<<<NB, 256>>>(yi, yit, (float*)d_out);
}

// round 4
// speedup vs baseline: 1.0588x; 1.0588x over previous
#include <cuda_runtime.h>
#include <stdint.h>

#define NPTS 256
#define DIM  256
#define KNN  16
#define NB   128        // 2 rows/block; 128 <= 148 SMs -> single wave, spin barrier safe
#define EPSV 1e-12f

__device__ float g_Yn[NPTS * DIM];    // row-major normalized yi
__device__ float g_rn[NPTS];          // ||yn_j||^2
__device__ float g_part[NB];          // per-block loss partials
__device__ unsigned g_bar = 0, g_rel = 0, g_done = 0;

__global__ __launch_bounds__(256, 1)
void k_fused(const float* __restrict__ yi, const float* __restrict__ yit,
             float* __restrict__ out) {
    __shared__ float4   s4[DIM];       // (yn_r0, ytn_r0, yn_r1, ytn_r1) per channel
    __shared__ float4   sh4[8];
    __shared__ float2   sh2[8];
    __shared__ unsigned sk0[NPTS];     // d1 bit-keys, row r0
    __shared__ unsigned sk1[NPTS];     // d1 bit-keys, row r1
    __shared__ float    sh_sc[6];      // rn0 rn1 rt0 rt1 dself0 dself1
    __shared__ float    shred[8];
    __shared__ unsigned s_last;

    const int t = threadIdx.x, b = blockIdx.x;
    const int r0 = 2 * b, r1 = r0 + 1;
    const int w = t >> 5, l = t & 31;

    unsigned epoch = 0;
    if (t == 0) epoch = *((volatile unsigned*)&g_rel);

    // ---------------- Phase A: normalize rows r0, r1 ----------------
    float a0 = yi [r0 * DIM + t], c0 = yit[r0 * DIM + t];
    float a1 = yi [r1 * DIM + t], c1 = yit[r1 * DIM + t];

    float4 p = make_float4(a0 * a0, c0 * c0, a1 * a1, c1 * c1);
    #pragma unroll
    for (int o = 16; o; o >>= 1) {
        p.x += __shfl_down_sync(0xffffffffu, p.x, o);
        p.y += __shfl_down_sync(0xffffffffu, p.y, o);
        p.z += __shfl_down_sync(0xffffffffu, p.z, o);
        p.w += __shfl_down_sync(0xffffffffu, p.w, o);
    }
    if (l == 0) sh4[w] = p;
    __syncthreads();
    if (w == 0) {
        float4 q = (l < 8) ? sh4[l] : make_float4(0.f, 0.f, 0.f, 0.f);
        #pragma unroll
        for (int o = 4; o; o >>= 1) {
            q.x += __shfl_down_sync(0xffffffffu, q.x, o);
            q.y += __shfl_down_sync(0xffffffffu, q.y, o);
            q.z += __shfl_down_sync(0xffffffffu, q.z, o);
            q.w += __shfl_down_sync(0xffffffffu, q.w, o);
        }
        if (l == 0) sh4[0] = q;
    }
    __syncthreads();
    float4 S = sh4[0];                  // sa0, sc0, sa1, sc1

    float ia0 = 1.0f / sqrtf(S.x + EPSV), ic0 = 1.0f / sqrtf(S.y + EPSV);
    float ia1 = 1.0f / sqrtf(S.z + EPSV), ic1 = 1.0f / sqrtf(S.w + EPSV);
    float an0 = a0 * ia0, cn0 = c0 * ic0;
    float an1 = a1 * ia1, cn1 = c1 * ic1;

    g_Yn[r0 * DIM + t] = an0;
    g_Yn[r1 * DIM + t] = an1;
    s4[t] = make_float4(an0, cn0, an1, cn1);

    float d0 = an0 - cn0, d1x = an1 - cn1;
    float2 p2 = make_float2(d0 * d0, d1x * d1x);
    #pragma unroll
    for (int o = 16; o; o >>= 1) {
        p2.x += __shfl_down_sync(0xffffffffu, p2.x, o);
        p2.y += __shfl_down_sync(0xffffffffu, p2.y, o);
    }
    if (l == 0) sh2[w] = p2;
    __syncthreads();
    if (t == 0) {
        float sd0 = 0.f, sd1 = 0.f;
        #pragma unroll
        for (int m = 0; m < 8; m++) { sd0 += sh2[m].x; sd1 += sh2[m].y; }
        float rn0 = S.x * ia0 * ia0, rn1 = S.z * ia1 * ia1;
        sh_sc[0] = rn0;              sh_sc[1] = rn1;
        sh_sc[2] = S.y * ic0 * ic0;  sh_sc[3] = S.w * ic1 * ic1;
        sh_sc[4] = 0.5f * sqrtf(sd0 + EPSV);
        sh_sc[5] = 0.5f * sqrtf(sd1 + EPSV);
        g_rn[r0] = rn0;              g_rn[r1] = rn1;
    }

    // ---------------- software grid barrier (tight spin, no nanosleep) ----------------
    __threadfence();
    __syncthreads();
    if (t == 0) {
        unsigned arrived = atomicAdd(&g_bar, 1);
        if (arrived == NB - 1) {
            *((volatile unsigned*)&g_bar) = 0;   // reset for next replay
            __threadfence();
            atomicAdd(&g_rel, 1);
        } else {
            while (*((volatile unsigned*)&g_rel) == epoch) { }
        }
        __threadfence();
    }
    __syncthreads();

    // ---------------- Phase B: thread t = column j; 4 dot products ----------------
    const float4* __restrict__ vrow = (const float4*)(g_Yn) + t * (DIM / 4);
    float accn0 = 0.f, acct0 = 0.f, accn1 = 0.f, acct1 = 0.f;
    #pragma unroll 8
    for (int c4 = 0; c4 < DIM / 4; c4++) {
        float4 v  = vrow[c4];
        float4 s0 = s4[4 * c4 + 0];
        float4 s1 = s4[4 * c4 + 1];
        float4 s2 = s4[4 * c4 + 2];
        float4 s3 = s4[4 * c4 + 3];
        accn0 = fmaf(s0.x, v.x, accn0); accn0 = fmaf(s1.x, v.y, accn0);
        accn0 = fmaf(s2.x, v.z, accn0); accn0 = fmaf(s3.x, v.w, accn0);
        acct0 = fmaf(s0.y, v.x, acct0); acct0 = fmaf(s1.y, v.y, acct0);
        acct0 = fmaf(s2.y, v.z, acct0); acct0 = fmaf(s3.y, v.w, acct0);
        accn1 = fmaf(s0.z, v.x, accn1); accn1 = fmaf(s1.z, v.y, accn1);
        accn1 = fmaf(s2.z, v.z, accn1); accn1 = fmaf(s3.z, v.w, accn1);
        acct1 = fmaf(s0.w, v.x, acct1); acct1 = fmaf(s1.w, v.y, acct1);
        acct1 = fmaf(s2.w, v.z, acct1); acct1 = fmaf(s3.w, v.w, acct1);
    }
    float rnj = *((volatile float*)&g_rn[t]);
    float rn0 = sh_sc[0], rn1 = sh_sc[1], rt0 = sh_sc[2], rt1 = sh_sc[3];
    float d1_0 = 0.5f * sqrtf(fmaxf(rn0 + rnj - 2.f * accn0, 0.f) + EPSV);
    float d2_0 = 0.5f * sqrtf(fmaxf(rt0 + rnj - 2.f * acct0, 0.f) + EPSV);
    float d1_1 = 0.5f * sqrtf(fmaxf(rn1 + rnj - 2.f * accn1, 0.f) + EPSV);
    float d2_1 = 0.5f * sqrtf(fmaxf(rt1 + rnj - 2.f * acct1, 0.f) + EPSV);

    // positive floats: u32 bit order == float order
    unsigned k0 = __float_as_uint(d1_0);
    unsigned k1 = __float_as_uint(d1_1);
    sk0[t] = k0;
    sk1[t] = k1;
    __syncthreads();

    // ---------------- Parallel rank-count selection ----------------
    // rank(t) = #{j : key_j < key_t}. Self-distance (~1.6e-6) is always the row
    // minimum -> rank 0 = self, ranks 1..16 = the K neighbors, rank 1 = second_nn.
    int rc0 = 0, rc1 = 0;
    const uint4* q0 = (const uint4*)sk0;
    const uint4* q1 = (const uint4*)sk1;
    #pragma unroll 8
    for (int q = 0; q < NPTS / 4; q++) {
        uint4 v0 = q0[q];                    // broadcast LDS.128
        rc0 += (v0.x < k0) + (v0.y < k0) + (v0.z < k0) + (v0.w < k0);
        uint4 v1 = q1[q];
        rc1 += (v1.x < k1) + (v1.y < k1) + (v1.z < k1) + (v1.w < k1);
    }

    float contrib = 0.f;
    if (rc0 >= 1 && rc0 <= KNN) {
        float df = d1_0 - d2_0;
        contrib = df * df;
        if (rc0 == 1) contrib += fmaxf(sh_sc[4] + 0.6f - d1_0, 0.f);
    }
    if (rc1 >= 1 && rc1 <= KNN) {
        float df = d1_1 - d2_1;
        contrib += df * df;
        if (rc1 == 1) contrib += fmaxf(sh_sc[5] + 0.6f - d1_1, 0.f);
    }

    // block reduce contrib -> per-block partial
    #pragma unroll
    for (int o = 16; o; o >>= 1) contrib += __shfl_down_sync(0xffffffffu, contrib, o);
    if (l == 0) shred[w] = contrib;
    __syncthreads();
    if (t == 0) {
        float s = 0.f;
        #pragma unroll
        for (int m = 0; m < 8; m++) s += shred[m];
        g_part[b] = s - 2.0f * (float)KNN * 0.0025f;   // two rows' -K*T
    }

    // ---------------- last arriving block: deterministic final reduce ----------------
    __threadfence();
    __syncthreads();
    if (t == 0) s_last = atomicAdd(&g_done, 1);
    __syncthreads();
    if (s_last == NB - 1) {
        float v = (t < NB) ? *((volatile float*)&g_part[t]) : 0.f;
        #pragma unroll
        for (int o = 16; o; o >>= 1) v += __shfl_down_sync(0xffffffffu, v, o);
        if (l == 0) shred[w] = v;
        __syncthreads();
        if (t == 0) {
            float s = 0.f;
            #pragma unroll
            for (int m = 0; m < 8; m++) s += shred[m];
            out[0] = s;
            *((volatile unsigned*)&g_done) = 0;       // reset for next replay
        }
    }
}

extern "C" void kernel_launch(void* const* d_in, const int* in_sizes, int n_in,
                              void* d_out, int out_size) {
    const float* yi  = (const float*)d_in[0];
    const float* yit = (const float*)d_in[1];
    k_fused<<<NB, 256>>>(yi, yit, (float*)d_out);
}

// round 5
// speedup vs baseline: 1.1462x; 1.0825x over previous
#include <cuda_runtime.h>
#include <stdint.h>

#define NPTS 256
#define DIM  256
#define KNN  16
#define NB   128        // 2 rows per block; blocks fully independent now
#define EPSV 1e-12f

__device__ float    g_part[NB];
__device__ unsigned g_done = 0;

__global__ __launch_bounds__(256, 1)
void k_fused(const float* __restrict__ yi, const float* __restrict__ yit,
             float* __restrict__ out) {
    __shared__ float4   s4[DIM];     // (yn_r0, ytn_r0, yn_r1, ytn_r1) per channel
    __shared__ float4   sh4[8];
    __shared__ float2   sh2[8];
    __shared__ unsigned sk0[NPTS];   // d1 bit-keys row r0
    __shared__ unsigned sk1[NPTS];   // d1 bit-keys row r1
    __shared__ float    sh_sc[6];    // rn0 rn1 rt0 rt1 dself0 dself1
    __shared__ float    shred[8];
    __shared__ unsigned s_last;

    const int t = threadIdx.x, b = blockIdx.x;
    const int r0 = 2 * b, r1 = r0 + 1;
    const int w = t >> 5, l = t & 31;

    // ---------------- Phase A: normalize this block's 2 rows (block-local) ----------------
    float a0 = yi [r0 * DIM + t], c0 = yit[r0 * DIM + t];
    float a1 = yi [r1 * DIM + t], c1 = yit[r1 * DIM + t];

    float4 p = make_float4(a0 * a0, c0 * c0, a1 * a1, c1 * c1);
    #pragma unroll
    for (int o = 16; o; o >>= 1) {
        p.x += __shfl_down_sync(0xffffffffu, p.x, o);
        p.y += __shfl_down_sync(0xffffffffu, p.y, o);
        p.z += __shfl_down_sync(0xffffffffu, p.z, o);
        p.w += __shfl_down_sync(0xffffffffu, p.w, o);
    }
    if (l == 0) sh4[w] = p;
    __syncthreads();
    if (w == 0) {
        float4 q = (l < 8) ? sh4[l] : make_float4(0.f, 0.f, 0.f, 0.f);
        #pragma unroll
        for (int o = 4; o; o >>= 1) {
            q.x += __shfl_down_sync(0xffffffffu, q.x, o);
            q.y += __shfl_down_sync(0xffffffffu, q.y, o);
            q.z += __shfl_down_sync(0xffffffffu, q.z, o);
            q.w += __shfl_down_sync(0xffffffffu, q.w, o);
        }
        if (l == 0) sh4[0] = q;
    }
    __syncthreads();
    float4 S = sh4[0];                       // sa0 sc0 sa1 sc1

    float ia0 = 1.0f / sqrtf(S.x + EPSV), ic0 = 1.0f / sqrtf(S.y + EPSV);
    float ia1 = 1.0f / sqrtf(S.z + EPSV), ic1 = 1.0f / sqrtf(S.w + EPSV);
    float an0 = a0 * ia0, cn0 = c0 * ic0;
    float an1 = a1 * ia1, cn1 = c1 * ic1;
    s4[t] = make_float4(an0, cn0, an1, cn1);

    float d0 = an0 - cn0, d1x = an1 - cn1;
    float2 p2 = make_float2(d0 * d0, d1x * d1x);
    #pragma unroll
    for (int o = 16; o; o >>= 1) {
        p2.x += __shfl_down_sync(0xffffffffu, p2.x, o);
        p2.y += __shfl_down_sync(0xffffffffu, p2.y, o);
    }
    if (l == 0) sh2[w] = p2;
    __syncthreads();
    if (t == 0) {
        float sd0 = 0.f, sd1 = 0.f;
        #pragma unroll
        for (int m = 0; m < 8; m++) { sd0 += sh2[m].x; sd1 += sh2[m].y; }
        sh_sc[0] = S.x * ia0 * ia0;  sh_sc[1] = S.z * ia1 * ia1;
        sh_sc[2] = S.y * ic0 * ic0;  sh_sc[3] = S.w * ic1 * ic1;
        sh_sc[4] = 0.5f * sqrtf(sd0 + EPSV);
        sh_sc[5] = 0.5f * sqrtf(sd1 + EPSV);
    }
    __syncthreads();

    // ---------------- Phase B: fused norm + dual dot, packed f32x2 FMA ----------------
    // Thread t streams RAW yi row t once: accumulates sum-of-squares and the
    // 4 dot products against the block's normalized rows; norm factored out after.
    const float4*     vrow = (const float4*)(yi) + t * (DIM / 4);
    const ulonglong2* s2p  = (const ulonglong2*)s4;   // .x=(an0,cn0) .y=(an1,cn1)
    unsigned long long acc0 = 0ull, acc1 = 0ull;      // packed (n0,t0), (n1,t1)
    float ss = 0.f;

    #pragma unroll 8
    for (int c4 = 0; c4 < DIM / 4; c4++) {
        float4 v = vrow[c4];
        #pragma unroll
        for (int d = 0; d < 4; d++) {
            float vd = (d == 0) ? v.x : (d == 1) ? v.y : (d == 2) ? v.z : v.w;
            ulonglong2 sp = s2p[4 * c4 + d];
            unsigned long long vv;
            asm("mov.b64 %0, {%1, %1};" : "=l"(vv) : "f"(vd));
            asm("fma.rn.f32x2 %0, %1, %2, %0;" : "+l"(acc0) : "l"(sp.x), "l"(vv));
            asm("fma.rn.f32x2 %0, %1, %2, %0;" : "+l"(acc1) : "l"(sp.y), "l"(vv));
            ss = fmaf(vd, vd, ss);
        }
    }

    float ia  = 1.0f / sqrtf(ss + EPSV);
    float rnt = ss * ia * ia;
    float rawn0, rawt0, rawn1, rawt1;
    asm("mov.b64 {%0, %1}, %2;" : "=f"(rawn0), "=f"(rawt0) : "l"(acc0));
    asm("mov.b64 {%0, %1}, %2;" : "=f"(rawn1), "=f"(rawt1) : "l"(acc1));

    float rn0 = sh_sc[0], rn1 = sh_sc[1], rt0 = sh_sc[2], rt1 = sh_sc[3];
    float d1_0 = 0.5f * sqrtf(fmaxf(rn0 + rnt - 2.f * (rawn0 * ia), 0.f) + EPSV);
    float d2_0 = 0.5f * sqrtf(fmaxf(rt0 + rnt - 2.f * (rawt0 * ia), 0.f) + EPSV);
    float d1_1 = 0.5f * sqrtf(fmaxf(rn1 + rnt - 2.f * (rawn1 * ia), 0.f) + EPSV);
    float d2_1 = 0.5f * sqrtf(fmaxf(rt1 + rnt - 2.f * (rawt1 * ia), 0.f) + EPSV);

    unsigned k0 = __float_as_uint(d1_0);     // positive floats: bit order == value order
    unsigned k1 = __float_as_uint(d1_1);
    sk0[t] = k0;
    sk1[t] = k1;
    __syncthreads();

    // ---------------- Parallel rank-count selection ----------------
    // Self distance is the row minimum (residual <= ~1e-4 vs neighbors ~0.7),
    // so rank 0 = self, ranks 1..16 = K neighbors, rank 1 = second_nn.
    int rc0 = 0, rc1 = 0;
    const uint4* q0 = (const uint4*)sk0;
    const uint4* q1 = (const uint4*)sk1;
    #pragma unroll 8
    for (int q = 0; q < NPTS / 4; q++) {
        uint4 v0 = q0[q];
        rc0 += (v0.x < k0) + (v0.y < k0) + (v0.z < k0) + (v0.w < k0);
        uint4 v1 = q1[q];
        rc1 += (v1.x < k1) + (v1.y < k1) + (v1.z < k1) + (v1.w < k1);
    }

    float contrib = 0.f;
    if (rc0 >= 1 && rc0 <= KNN) {
        float df = d1_0 - d2_0;
        contrib = df * df;
        if (rc0 == 1) contrib += fmaxf(sh_sc[4] + 0.6f - d1_0, 0.f);
    }
    if (rc1 >= 1 && rc1 <= KNN) {
        float df = d1_1 - d2_1;
        contrib += df * df;
        if (rc1 == 1) contrib += fmaxf(sh_sc[5] + 0.6f - d1_1, 0.f);
    }

    #pragma unroll
    for (int o = 16; o; o >>= 1) contrib += __shfl_down_sync(0xffffffffu, contrib, o);
    if (l == 0) shred[w] = contrib;
    __syncthreads();
    if (t == 0) {
        float s = 0.f;
        #pragma unroll
        for (int m = 0; m < 8; m++) s += shred[m];
        g_part[b] = s - 2.0f * (float)KNN * 0.0025f;
    }

    // ---------------- last arriving block: deterministic final reduce ----------------
    __threadfence();
    __syncthreads();
    if (t == 0) s_last = atomicAdd(&g_done, 1);
    __syncthreads();
    if (s_last == NB - 1) {
        float v = (t < NB) ? *((volatile float*)&g_part[t]) : 0.f;
        #pragma unroll
        for (int o = 16; o; o >>= 1) v += __shfl_down_sync(0xffffffffu, v, o);
        if (l == 0) shred[w] = v;
        __syncthreads();
        if (t == 0) {
            float s = 0.f;
            #pragma unroll
            for (int m = 0; m < 8; m++) s += shred[m];
            out[0] = s;
            *((volatile unsigned*)&g_done) = 0;   // reset for next graph replay
        }
    }
}

extern "C" void kernel_launch(void* const* d_in, const int* in_sizes, int n_in,
                              void* d_out, int out_size) {
    const float* yi  = (const float*)d_in[0];
    const float* yit = (const float*)d_in[1];
    k_fused<<<NB, 256>>>(yi, yit, (float*)d_out);
}